// round 1
// baseline (speedup 1.0000x reference)
#include <cuda_runtime.h>
#include <cstdint>

#define B_ 64
#define T_ 96
#define NV 4
#define NK_ 12
#define NF_ 17
#define HW_ 400
#define SIGLEN_ 306
#define KTOT_ 122400        // HW_*SIGLEN_
#define NCHUNK_ 153
#define KC_ 800             // NCHUNK_*KC_ == KTOT_

// Scratch (static __device__ arrays; no allocation allowed in kernel_launch)
__device__ float g_feat[(size_t)B_ * T_ * NF_ * HW_];   // [b][t][f][p]  ~167 MB
__device__ float g_sig [(size_t)B_ * HW_ * SIGLEN_];    // [b][p][s]     ~31 MB
__device__ float g_part[(size_t)NCHUNK_ * 64 * 32];

// ---------------------------------------------------------------------------
// Kernel 1: conv3x3 (4->12, SAME) + copy x + time channel  -> g_feat
// One block per (b,t) image. 160 threads = 4 k-groups x 40 threads.
// Each thread: 3 output channels (weights in registers) x 10 pixels.
// ---------------------------------------------------------------------------
__global__ __launch_bounds__(160, 2)
void conv_kernel(const float* __restrict__ x,
                 const float* __restrict__ cw,
                 const float* __restrict__ cb)
{
    __shared__ float xs[4 * 484];   // 4 vars, padded 22x22
    __shared__ float ws[444];       // 432 weights + 12 bias

    const int bid = blockIdx.x;     // b*96 + t
    const int t   = bid % T_;
    const int tid = threadIdx.x;
    const float* xg = x + (size_t)bid * NV * HW_;

    for (int i = tid; i < 4 * 484; i += 160) {
        int v = i / 484, r = i % 484, yy = r / 22, xx = r % 22;
        float val = 0.f;
        if (yy >= 1 && yy <= 20 && xx >= 1 && xx <= 20)
            val = xg[v * HW_ + (yy - 1) * 20 + (xx - 1)];
        xs[i] = val;
    }
    for (int i = tid; i < 444; i += 160)
        ws[i] = (i < 432) ? cw[i] : cb[i - 432];
    __syncthreads();

    const int kg = tid / 40, lane = tid % 40;
    const int k0 = kg * 3, p0 = lane * 10;

    float wr[3][36];
#pragma unroll
    for (int kk = 0; kk < 3; kk++)
#pragma unroll
        for (int tap = 0; tap < 36; tap++)
            wr[kk][tap] = ws[(k0 + kk) * 36 + tap];
    const float bi0 = ws[432 + k0], bi1 = ws[432 + k0 + 1], bi2 = ws[432 + k0 + 2];

    float* fo = g_feat + (size_t)bid * NF_ * HW_;

    for (int p = 0; p < 10; p++) {
        const int pg = p0 + p;
        const int y = pg / 20, xc = pg % 20;
        const float* base = xs + y * 22 + xc;   // tap (dy,dx) -> padded (y+dy, xc+dx)
        float a0 = bi0, a1 = bi1, a2 = bi2;
#pragma unroll
        for (int v = 0; v < 4; v++)
#pragma unroll
            for (int dy = 0; dy < 3; dy++)
#pragma unroll
                for (int dx = 0; dx < 3; dx++) {
                    const float xv = base[v * 484 + dy * 22 + dx];
                    const int tap = v * 9 + dy * 3 + dx;
                    a0 = fmaf(wr[0][tap], xv, a0);
                    a1 = fmaf(wr[1][tap], xv, a1);
                    a2 = fmaf(wr[2][tap], xv, a2);
                }
        fo[(k0 + 0) * HW_ + pg] = a0;
        fo[(k0 + 1) * HW_ + pg] = a1;
        fo[(k0 + 2) * HW_ + pg] = a2;
    }

    // features 12..15 = x vars, 16 = time channel
    const float tval = (float)t * (1.0f / 95.0f);
    for (int i = tid; i < 5 * HW_; i += 160) {
        const int f = 12 + i / HW_, pg = i % HW_;
        float val;
        if (f < 16) {
            const int v = f - 12;
            val = xs[v * 484 + (pg / 20 + 1) * 22 + (pg % 20 + 1)];
        } else val = tval;
        fo[f * HW_ + pg] = val;
    }
}

// ---------------------------------------------------------------------------
// Kernel 2: path signature.
// lvl1_j = p_{95,j} - p_{0,j}
// lvl2_ij = 0.5 * sum_t (p_t + p_{t-1})_i (p_t - p_{t-1})_j  -  p0_i * lvl1_j
// Block = 400 threads, 100 pixels, 4 threads/pixel each owning a 9x9 (i,j)
// quadrant (i0,j0 in {0,8}; row/col 8 redundantly computed, identical values).
// ---------------------------------------------------------------------------
__global__ __launch_bounds__(400, 1)
void sig_kernel()
{
    __shared__ float cur[2][17 * 101];

    const int b = blockIdx.y, cx = blockIdx.x;
    const int pbase = cx * 100;
    const int tid = threadIdx.x;
    const int pp = tid >> 2, q = tid & 3;
    const int i0 = (q >> 1) * 8, j0 = (q & 1) * 8;

    const float* fb = g_feat + (size_t)b * T_ * NF_ * HW_ + pbase;

    // t = 0
    for (int i = tid; i < 17 * 100; i += 400) {
        const int f = i / 100, p = i % 100;
        cur[0][f * 101 + p] = fb[f * HW_ + p];
    }
    __syncthreads();

    float pi[9], pj[9], acc[9][9];
#pragma unroll
    for (int a = 0; a < 9; a++) pi[a] = cur[0][(i0 + a) * 101 + pp];
#pragma unroll
    for (int c = 0; c < 9; c++) pj[c] = cur[0][(j0 + c) * 101 + pp];
#pragma unroll
    for (int a = 0; a < 9; a++)
#pragma unroll
        for (int c = 0; c < 9; c++) acc[a][c] = 0.f;

    for (int t = 1; t < T_; t++) {
        const int buf = t & 1;
        const float* ft = fb + (size_t)t * NF_ * HW_;
        for (int i = tid; i < 17 * 100; i += 400) {
            const int f = i / 100, p = i % 100;
            cur[buf][f * 101 + p] = ft[f * HW_ + p];
        }
        __syncthreads();

        float m[9];
#pragma unroll
        for (int a = 0; a < 9; a++) {
            const float cv = cur[buf][(i0 + a) * 101 + pp];
            m[a] = cv + pi[a];   // (p_t + p_{t-1})_i   (0.5 deferred)
            pi[a] = cv;
        }
#pragma unroll
        for (int c = 0; c < 9; c++) {
            const float cv = cur[buf][(j0 + c) * 101 + pp];
            const float d = cv - pj[c];
            pj[c] = cv;
#pragma unroll
            for (int a = 0; a < 9; a++)
                acc[a][c] = fmaf(m[a], d, acc[a][c]);
        }
    }

    // epilogue: re-read p0 from gmem (cheap), assemble signature
    float p0i[9], l1[9];
#pragma unroll
    for (int a = 0; a < 9; a++) p0i[a] = fb[(i0 + a) * HW_ + pp];
#pragma unroll
    for (int c = 0; c < 9; c++) {
        const float p0j = fb[(j0 + c) * HW_ + pp];
        l1[c] = pj[c] - p0j;
    }

    float* sg = g_sig + ((size_t)b * HW_ + pbase + pp) * SIGLEN_;
    if (q < 2) {
#pragma unroll
        for (int c = 0; c < 9; c++) sg[j0 + c] = l1[c];
    }
#pragma unroll
    for (int a = 0; a < 9; a++)
#pragma unroll
        for (int c = 0; c < 9; c++)
            sg[17 + (i0 + a) * 17 + (j0 + c)] = 0.5f * acc[a][c] - p0i[a] * l1[c];
}

// ---------------------------------------------------------------------------
// Kernel 3: layer-1 GEMM partials: out1[64,32] over K=122400, K split into
// 153 chunks of 800. Block: 256 threads, thread owns 2b x 4o. Deterministic
// partial buffer (no float atomics).
// ---------------------------------------------------------------------------
__global__ __launch_bounds__(256)
void mlp1_kernel(const float* __restrict__ w1)
{
    __shared__ __align__(16) float ss[32 * 66];
    __shared__ __align__(16) float wsm[32 * 32];

    const int cx = blockIdx.x, tid = threadIdx.x;
    const int oq = tid & 7, bq = tid >> 3;
    const int b0 = bq * 2, o0 = oq * 4;
    const int kb = cx * KC_;

    float acc[2][4] = {};

    for (int tile = 0; tile < KC_ / 32; tile++) {
        const int k0 = kb + tile * 32;
#pragma unroll
        for (int r = 0; r < 8; r++) {
            const int idx = tid + r * 256;
            const int bb = idx >> 5, kk = idx & 31;
            ss[kk * 66 + bb] = g_sig[(size_t)bb * KTOT_ + k0 + kk];
        }
#pragma unroll
        for (int r = 0; r < 4; r++) {
            const int idx = tid + r * 256;
            const int kk = idx >> 5, oo = idx & 31;
            wsm[kk * 32 + oo] = w1[(size_t)(k0 + kk) * 32 + oo];
        }
        __syncthreads();
#pragma unroll
        for (int kk = 0; kk < 32; kk++) {
            const float2 sv = *(const float2*)&ss[kk * 66 + b0];
            const float4 wv = *(const float4*)&wsm[kk * 32 + o0];
            acc[0][0] = fmaf(sv.x, wv.x, acc[0][0]);
            acc[0][1] = fmaf(sv.x, wv.y, acc[0][1]);
            acc[0][2] = fmaf(sv.x, wv.z, acc[0][2]);
            acc[0][3] = fmaf(sv.x, wv.w, acc[0][3]);
            acc[1][0] = fmaf(sv.y, wv.x, acc[1][0]);
            acc[1][1] = fmaf(sv.y, wv.y, acc[1][1]);
            acc[1][2] = fmaf(sv.y, wv.z, acc[1][2]);
            acc[1][3] = fmaf(sv.y, wv.w, acc[1][3]);
        }
        __syncthreads();
    }
#pragma unroll
    for (int i = 0; i < 2; i++)
#pragma unroll
        for (int j = 0; j < 4; j++)
            g_part[((size_t)cx * 64 + b0 + i) * 32 + o0 + j] = acc[i][j];
}

// ---------------------------------------------------------------------------
// Kernel 4: reduce partials + bias/relu + layers 2..4. Grid 64 (b), 32 thr.
// ---------------------------------------------------------------------------
__global__ void mlp_tail_kernel(const float* __restrict__ b1,
                                const float* __restrict__ w2, const float* __restrict__ b2,
                                const float* __restrict__ w3, const float* __restrict__ b3,
                                const float* __restrict__ w4, const float* __restrict__ b4,
                                float* __restrict__ out)
{
    const int b = blockIdx.x, o = threadIdx.x;
    float s = b1[o];
    for (int c = 0; c < NCHUNK_; c++) s += g_part[((size_t)c * 64 + b) * 32 + o];

    __shared__ float hs[32];
    hs[o] = fmaxf(s, 0.f);
    __syncthreads();

    float s2 = b2[o];
#pragma unroll
    for (int k = 0; k < 32; k++) s2 = fmaf(hs[k], w2[k * 32 + o], s2);
    __syncthreads();
    hs[o] = fmaxf(s2, 0.f);
    __syncthreads();

    float s3 = b3[o];
#pragma unroll
    for (int k = 0; k < 32; k++) s3 = fmaf(hs[k], w3[k * 32 + o], s3);
    __syncthreads();
    hs[o] = fmaxf(s3, 0.f);
    __syncthreads();

    float v = hs[o] * w4[o];
#pragma unroll
    for (int off = 16; off; off >>= 1) v += __shfl_xor_sync(0xffffffffu, v, off);
    if (o == 0) out[b] = v + b4[0];
}

// ---------------------------------------------------------------------------
extern "C" void kernel_launch(void* const* d_in, const int* in_sizes, int n_in,
                              void* d_out, int out_size)
{
    const float* x  = (const float*)d_in[0];
    const float* cw = (const float*)d_in[1];
    const float* cb = (const float*)d_in[2];
    const float* w1 = (const float*)d_in[3];
    const float* b1 = (const float*)d_in[4];
    const float* w2 = (const float*)d_in[5];
    const float* b2 = (const float*)d_in[6];
    const float* w3 = (const float*)d_in[7];
    const float* b3 = (const float*)d_in[8];
    const float* w4 = (const float*)d_in[9];
    const float* b4 = (const float*)d_in[10];
    float* out = (float*)d_out;

    conv_kernel<<<B_ * T_, 160>>>(x, cw, cb);
    sig_kernel<<<dim3(4, B_), 400>>>();
    mlp1_kernel<<<NCHUNK_, 256>>>(w1);
    mlp_tail_kernel<<<B_, 32>>>(b1, w2, b2, w3, b3, w4, b4, out);
}

// round 2
// speedup vs baseline: 1.9844x; 1.9844x over previous
#include <cuda_runtime.h>
#include <cstdint>

#define B_ 64
#define T_ 96
#define NV 4
#define NK_ 12
#define NF_ 17
#define HW_ 400
#define SIGLEN_ 306
#define KTOT_ 122400        // HW_*SIGLEN_
#define NCHUNK_ 255
#define KC_ 480             // NCHUNK_*KC_ == KTOT_

// Scratch (static __device__ arrays; no allocation allowed in kernel_launch)
__device__ float g_feat[(size_t)B_ * T_ * NF_ * HW_];   // [b][t][f][p]  ~167 MB
__device__ float g_sig [(size_t)B_ * HW_ * SIGLEN_];    // [b][p][s]     ~31 MB
__device__ float g_part[(size_t)NCHUNK_ * 64 * 32];

// ---------------------------------------------------------------------------
// Kernel 1: conv3x3 (4->12, SAME) + copy x + time channel  -> g_feat
// One block per (b,t) image. 160 threads = 4 k-groups x 40 threads.
// Thread handles 3 output channels (weights in regs) x 10 pixels with
// CONTIGUOUS lane->pixel mapping (pg = lane + 40*p) for coalesced stores.
// ---------------------------------------------------------------------------
__global__ __launch_bounds__(160, 2)
void conv_kernel(const float* __restrict__ x,
                 const float* __restrict__ cw,
                 const float* __restrict__ cb)
{
    __shared__ float xs[4 * 484];   // 4 vars, padded 22x22
    __shared__ float ws[444];       // 432 weights + 12 bias

    const int bid = blockIdx.x;     // b*96 + t
    const int t   = bid % T_;
    const int tid = threadIdx.x;
    const float* xg = x + (size_t)bid * NV * HW_;

    for (int i = tid; i < 4 * 484; i += 160) {
        int v = i / 484, r = i % 484, yy = r / 22, xx = r % 22;
        float val = 0.f;
        if (yy >= 1 && yy <= 20 && xx >= 1 && xx <= 20)
            val = xg[v * HW_ + (yy - 1) * 20 + (xx - 1)];
        xs[i] = val;
    }
    for (int i = tid; i < 444; i += 160)
        ws[i] = (i < 432) ? cw[i] : cb[i - 432];
    __syncthreads();

    const int kg = tid / 40, lane = tid % 40;
    const int k0 = kg * 3;
    const int y0 = lane / 20, xc = lane % 20;   // hoisted out of pixel loop

    float wr[3][36];
#pragma unroll
    for (int kk = 0; kk < 3; kk++)
#pragma unroll
        for (int tap = 0; tap < 36; tap++)
            wr[kk][tap] = ws[(k0 + kk) * 36 + tap];
    const float bi0 = ws[432 + k0], bi1 = ws[432 + k0 + 1], bi2 = ws[432 + k0 + 2];

    float* fo = g_feat + (size_t)bid * NF_ * HW_;

#pragma unroll
    for (int p = 0; p < 10; p++) {
        const float* base = xs + (y0 + 2 * p) * 22 + xc;
        float a0 = bi0, a1 = bi1, a2 = bi2;
#pragma unroll
        for (int v = 0; v < 4; v++)
#pragma unroll
            for (int dy = 0; dy < 3; dy++)
#pragma unroll
                for (int dx = 0; dx < 3; dx++) {
                    const float xv = base[v * 484 + dy * 22 + dx];
                    const int tap = v * 9 + dy * 3 + dx;
                    a0 = fmaf(wr[0][tap], xv, a0);
                    a1 = fmaf(wr[1][tap], xv, a1);
                    a2 = fmaf(wr[2][tap], xv, a2);
                }
        const int pg = lane + 40 * p;   // lanes contiguous -> coalesced stores
        fo[(k0 + 0) * HW_ + pg] = a0;
        fo[(k0 + 1) * HW_ + pg] = a1;
        fo[(k0 + 2) * HW_ + pg] = a2;
    }

    // features 12..15 = x vars, 16 = time channel (coalesced)
    const float tval = (float)t * (1.0f / 95.0f);
    for (int i = tid; i < 5 * HW_; i += 160) {
        const int f = 12 + i / HW_, pg = i % HW_;
        float val;
        if (f < 16) {
            const int v = f - 12;
            val = xs[v * 484 + (pg / 20 + 1) * 22 + (pg % 20 + 1)];
        } else val = tval;
        fo[f * HW_ + pg] = val;
    }
}

// ---------------------------------------------------------------------------
// Kernel 2: path signature.
// lvl1_j = p_{95,j} - p_{0,j}
// lvl2_ij = 0.5 * sum_t (p_t + p_{t-1})_i (p_t - p_{t-1})_j  -  p0_i * lvl1_j
// Block = 400 threads, 100 pixels, 4 threads/pixel each owning a 9x9 (i,j)
// quadrant. Load indices hoisted; gmem->reg prefetch pipeline hides latency.
// ---------------------------------------------------------------------------
__global__ __launch_bounds__(400, 1)
void sig_kernel()
{
    __shared__ float cur[2][17 * 101];

    const int b = blockIdx.y, cx = blockIdx.x;
    const int pbase = cx * 100;
    const int tid = threadIdx.x;
    const int pp = tid >> 2, q = tid & 3;
    const int i0 = (q >> 1) * 8, j0 = (q & 1) * 8;

    const float* fb = g_feat + (size_t)b * T_ * NF_ * HW_ + pbase;

    // Hoisted load offsets: elements tid, tid+400, ... (<1700); 5 if tid<100 else 4
    int goff[5], soff[5];
#pragma unroll
    for (int l = 0; l < 5; l++) {
        const int i = tid + l * 400;
        if (i < 1700) {
            const int f = i / 100, p = i - f * 100;
            goff[l] = f * HW_ + p;
            soff[l] = f * 101 + p;
        } else {
            goff[l] = -1; soff[l] = 0;
        }
    }

    // t = 0 load
#pragma unroll
    for (int l = 0; l < 5; l++)
        if (goff[l] >= 0) cur[0][soff[l]] = fb[goff[l]];
    __syncthreads();

    float pi[9], pj[9], acc[9][9];
#pragma unroll
    for (int a = 0; a < 9; a++) pi[a] = cur[0][(i0 + a) * 101 + pp];
#pragma unroll
    for (int c = 0; c < 9; c++) pj[c] = cur[0][(j0 + c) * 101 + pp];
#pragma unroll
    for (int a = 0; a < 9; a++)
#pragma unroll
        for (int c = 0; c < 9; c++) acc[a][c] = 0.f;

    // prefetch t=1 into registers
    float rv[5];
    {
        const float* fn = fb + (size_t)NF_ * HW_;
#pragma unroll
        for (int l = 0; l < 5; l++)
            if (goff[l] >= 0) rv[l] = fn[goff[l]];
    }

    for (int t = 1; t < T_; t++) {
        const int buf = t & 1;
#pragma unroll
        for (int l = 0; l < 5; l++)
            if (goff[l] >= 0) cur[buf][soff[l]] = rv[l];
        if (t < T_ - 1) {
            const float* fn = fb + (size_t)(t + 1) * NF_ * HW_;
#pragma unroll
            for (int l = 0; l < 5; l++)
                if (goff[l] >= 0) rv[l] = fn[goff[l]];
        }
        __syncthreads();

        float m[9];
#pragma unroll
        for (int a = 0; a < 9; a++) {
            const float cv = cur[buf][(i0 + a) * 101 + pp];
            m[a] = cv + pi[a];   // (p_t + p_{t-1})_i   (0.5 deferred)
            pi[a] = cv;
        }
#pragma unroll
        for (int c = 0; c < 9; c++) {
            const float cv = cur[buf][(j0 + c) * 101 + pp];
            const float d = cv - pj[c];
            pj[c] = cv;
#pragma unroll
            for (int a = 0; a < 9; a++)
                acc[a][c] = fmaf(m[a], d, acc[a][c]);
        }
    }

    // epilogue: re-read p0 from gmem (L2-resident), assemble signature
    float p0i[9], l1[9];
#pragma unroll
    for (int a = 0; a < 9; a++) p0i[a] = fb[(i0 + a) * HW_ + pp];
#pragma unroll
    for (int c = 0; c < 9; c++) {
        const float p0j = fb[(j0 + c) * HW_ + pp];
        l1[c] = pj[c] - p0j;
    }

    float* sg = g_sig + ((size_t)b * HW_ + pbase + pp) * SIGLEN_;
    if (q < 2) {
#pragma unroll
        for (int c = 0; c < 9; c++) sg[j0 + c] = l1[c];
    }
#pragma unroll
    for (int a = 0; a < 9; a++)
#pragma unroll
        for (int c = 0; c < 9; c++)
            sg[17 + (i0 + a) * 17 + (j0 + c)] = 0.5f * acc[a][c] - p0i[a] * l1[c];
}

// ---------------------------------------------------------------------------
// Kernel 3: layer-1 GEMM partials: out1[64,32] over K=122400, split into
// 255 chunks of 480 (15 K-tiles of 32). Register prefetch of next tile.
// Block: 256 threads, thread owns 2b x 4o. Deterministic partials.
// ---------------------------------------------------------------------------
__global__ __launch_bounds__(256)
void mlp1_kernel(const float* __restrict__ w1)
{
    __shared__ __align__(16) float ss[32 * 66];
    __shared__ __align__(16) float wsm[32 * 32];

    const int cx = blockIdx.x, tid = threadIdx.x;
    const int oq = tid & 7, bq = tid >> 3;
    const int b0 = bq * 2, o0 = oq * 4;
    const int kb = cx * KC_;

    // per-thread staging indices (compile-time unrolled)
    float ps[8], pw[4];
    {
        const int k0 = kb;
#pragma unroll
        for (int r = 0; r < 8; r++) {
            const int idx = tid + r * 256;
            ps[r] = g_sig[(size_t)(idx >> 5) * KTOT_ + k0 + (idx & 31)];
        }
#pragma unroll
        for (int r = 0; r < 4; r++) {
            const int idx = tid + r * 256;
            pw[r] = w1[(size_t)(k0 + (idx >> 5)) * 32 + (idx & 31)];
        }
    }

    float acc[2][4] = {};

    for (int tile = 0; tile < KC_ / 32; tile++) {
#pragma unroll
        for (int r = 0; r < 8; r++) {
            const int idx = tid + r * 256;
            ss[(idx & 31) * 66 + (idx >> 5)] = ps[r];
        }
#pragma unroll
        for (int r = 0; r < 4; r++) {
            const int idx = tid + r * 256;
            wsm[(idx >> 5) * 32 + (idx & 31)] = pw[r];
        }
        if (tile < KC_ / 32 - 1) {
            const int k0 = kb + (tile + 1) * 32;
#pragma unroll
            for (int r = 0; r < 8; r++) {
                const int idx = tid + r * 256;
                ps[r] = g_sig[(size_t)(idx >> 5) * KTOT_ + k0 + (idx & 31)];
            }
#pragma unroll
            for (int r = 0; r < 4; r++) {
                const int idx = tid + r * 256;
                pw[r] = w1[(size_t)(k0 + (idx >> 5)) * 32 + (idx & 31)];
            }
        }
        __syncthreads();
#pragma unroll
        for (int kk = 0; kk < 32; kk++) {
            const float2 sv = *(const float2*)&ss[kk * 66 + b0];
            const float4 wv = *(const float4*)&wsm[kk * 32 + o0];
            acc[0][0] = fmaf(sv.x, wv.x, acc[0][0]);
            acc[0][1] = fmaf(sv.x, wv.y, acc[0][1]);
            acc[0][2] = fmaf(sv.x, wv.z, acc[0][2]);
            acc[0][3] = fmaf(sv.x, wv.w, acc[0][3]);
            acc[1][0] = fmaf(sv.y, wv.x, acc[1][0]);
            acc[1][1] = fmaf(sv.y, wv.y, acc[1][1]);
            acc[1][2] = fmaf(sv.y, wv.z, acc[1][2]);
            acc[1][3] = fmaf(sv.y, wv.w, acc[1][3]);
        }
        __syncthreads();
    }
#pragma unroll
    for (int i = 0; i < 2; i++)
#pragma unroll
        for (int j = 0; j < 4; j++)
            g_part[((size_t)cx * 64 + b0 + i) * 32 + o0 + j] = acc[i][j];
}

// ---------------------------------------------------------------------------
// Kernel 4: reduce partials (256 threads) + bias/relu + layers 2..4 in warp 0
// via shuffles (no smem sync among a partial warp). Grid 64 (b).
// ---------------------------------------------------------------------------
__global__ __launch_bounds__(256)
void mlp_tail_kernel(const float* __restrict__ b1,
                     const float* __restrict__ w2, const float* __restrict__ b2,
                     const float* __restrict__ w3, const float* __restrict__ b3,
                     const float* __restrict__ w4, const float* __restrict__ b4,
                     float* __restrict__ out)
{
    __shared__ float red[8][33];
    const int b = blockIdx.x, tid = threadIdx.x;
    const int o = tid & 31, g = tid >> 5;

    float s = 0.f;
    for (int c = g; c < NCHUNK_; c += 8)
        s += g_part[((size_t)c * 64 + b) * 32 + o];
    red[g][o] = s;
    __syncthreads();

    if (tid < 32) {
        float s1 = b1[o];
#pragma unroll
        for (int gg = 0; gg < 8; gg++) s1 += red[gg][o];
        float h = fmaxf(s1, 0.f);

        float s2 = b2[o];
#pragma unroll
        for (int k = 0; k < 32; k++)
            s2 = fmaf(__shfl_sync(0xffffffffu, h, k), w2[k * 32 + o], s2);
        h = fmaxf(s2, 0.f);

        float s3 = b3[o];
#pragma unroll
        for (int k = 0; k < 32; k++)
            s3 = fmaf(__shfl_sync(0xffffffffu, h, k), w3[k * 32 + o], s3);
        h = fmaxf(s3, 0.f);

        float v = h * w4[o];
#pragma unroll
        for (int off = 16; off; off >>= 1) v += __shfl_xor_sync(0xffffffffu, v, off);
        if (o == 0) out[b] = v + b4[0];
    }
}

// ---------------------------------------------------------------------------
extern "C" void kernel_launch(void* const* d_in, const int* in_sizes, int n_in,
                              void* d_out, int out_size)
{
    const float* x  = (const float*)d_in[0];
    const float* cw = (const float*)d_in[1];
    const float* cb = (const float*)d_in[2];
    const float* w1 = (const float*)d_in[3];
    const float* b1 = (const float*)d_in[4];
    const float* w2 = (const float*)d_in[5];
    const float* b2 = (const float*)d_in[6];
    const float* w3 = (const float*)d_in[7];
    const float* b3 = (const float*)d_in[8];
    const float* w4 = (const float*)d_in[9];
    const float* b4 = (const float*)d_in[10];
    float* out = (float*)d_out;

    conv_kernel<<<B_ * T_, 160>>>(x, cw, cb);
    sig_kernel<<<dim3(4, B_), 400>>>();
    mlp1_kernel<<<NCHUNK_, 256>>>(w1);
    mlp_tail_kernel<<<B_, 32 * 8>>>(b1, w2, b2, w3, b3, w4, b4, out);
}